// round 13
// baseline (speedup 1.0000x reference)
#include <cuda_runtime.h>
#include <cstdint>

#define N_SAMPLES 2048
#define N_CHAN    512
#define HW        49
#define N_GROUPS  64
#define CHB       32                        // channels/chunk: strip 6272B, 128B-aligned
#define QCH       (N_CHAN / CHB)            // 16
#define WSZ       16                        // members per window slot
#define WPG       4                         // slots per group (slot 3 = remainder)
#define GRID      (N_GROUPS * WPG * QCH)    // 4096
#define THREADS   256
#define STRIP_F4  392                       // CHB*HW/4
#define SAMPLE_F4 (N_CHAN * HW / 4)         // 6272
#define CTAS_PER_GROUP (WPG * QCH)          // 64 arrivals per group

// Device scratch. g_flag/g_arr are zero at load and self-reset every replay.
__device__ unsigned short g_list[N_GROUPS][N_SAMPLES];
__device__ int            g_cnt[N_GROUPS];
__device__ float          g_recip[N_GROUPS];
__device__ int            g_flag[N_GROUPS];
__device__ int            g_arr[N_GROUPS];

// Single fused kernel. bid<64: build group bid's list + zero its out row,
// release flag. Everyone: wait flag for streamed group, run the R10 hot loop
// (window slot of <=16 members, 32-channel 128B-aligned strips, LDG.128 x8
// front batch), prescaled atomicAdd, then arrive (last arrival resets flag).
__global__ __launch_bounds__(THREADS, 5) void fused_kernel(
    const float* __restrict__ x,
    const int*   __restrict__ idx,
    float*       __restrict__ out)
{
    __shared__ float4 red4[STRIP_F4];           // 6272 B
    __shared__ int    s_cnt;

    const int bid  = blockIdx.x;
    const int tid  = threadIdx.x;
    const int q    = bid & (QCH - 1);
    const int g    = (bid >> 4) & (N_GROUPS - 1);
    const int slot = bid >> 10;                  // slowest: dead slots at end

    // ---------------- prep phase (first 64 CTAs) ----------------
    if (bid < N_GROUPS) {
        const int pg = bid;
        if (tid == 0) s_cnt = 0;
        __syncthreads();

        const int4* __restrict__ idx4 = (const int4*)idx;
        for (int i = tid; i < N_SAMPLES / 4; i += THREADS) {
            int4 v = idx4[i];
            int  b = 4 * i;
            if (v.x == pg) g_list[pg][atomicAdd(&s_cnt, 1)] = (unsigned short)(b + 0);
            if (v.y == pg) g_list[pg][atomicAdd(&s_cnt, 1)] = (unsigned short)(b + 1);
            if (v.z == pg) g_list[pg][atomicAdd(&s_cnt, 1)] = (unsigned short)(b + 2);
            if (v.w == pg) g_list[pg][atomicAdd(&s_cnt, 1)] = (unsigned short)(b + 3);
        }
        __syncthreads();
        if (tid == 0) {
            g_cnt[pg]   = s_cnt;
            g_recip[pg] = 1.0f / ((float)s_cnt * (float)HW);
        }
        float4* o4 = (float4*)(out + pg * N_CHAN);
        if (tid < N_CHAN / 4) o4[tid] = make_float4(0.f, 0.f, 0.f, 0.f);

        __threadfence();                         // all writes -> L2
        __syncthreads();
        if (tid == 0) atomicExch(&g_flag[pg], 1);   // release
    }

    // ---------------- wait for my streamed group ----------------
    if (tid == 0) {
        while (atomicAdd(&g_flag[g], 0) == 0) __nanosleep(64);
    }
    __syncthreads();                             // block-wide acquire point

    const int cnt   = g_cnt[g];
    const int start = slot * WSZ;
    int len = cnt - start;

    if (len > 0) {
        if (slot < WPG - 1 && len > WSZ) len = WSZ;   // slot 3 = remainder

        const unsigned short* __restrict__ lst = &g_list[g][start];
        const float4* __restrict__ xq = (const float4*)x + (size_t)q * STRIP_F4;
        const bool hi = (tid < STRIP_F4 - THREADS);   // tid < 136

        float4 a0 = make_float4(0.f, 0.f, 0.f, 0.f);
        float4 a1 = make_float4(0.f, 0.f, 0.f, 0.f);

        int i = 0;
        for (; i + 4 <= len; i += 4) {           // 4 members front-batched
            const float4* b0 = xq + (size_t)lst[i + 0] * SAMPLE_F4;
            const float4* b1 = xq + (size_t)lst[i + 1] * SAMPLE_F4;
            const float4* b2 = xq + (size_t)lst[i + 2] * SAMPLE_F4;
            const float4* b3 = xq + (size_t)lst[i + 3] * SAMPLE_F4;
            float4 v0 = __ldg(b0 + tid);
            float4 v1 = __ldg(b1 + tid);
            float4 v2 = __ldg(b2 + tid);
            float4 v3 = __ldg(b3 + tid);
            float4 u0, u1, u2, u3;
            if (hi) {
                u0 = __ldg(b0 + THREADS + tid);
                u1 = __ldg(b1 + THREADS + tid);
                u2 = __ldg(b2 + THREADS + tid);
                u3 = __ldg(b3 + THREADS + tid);
            }
            a0.x += v0.x + v1.x + v2.x + v3.x;
            a0.y += v0.y + v1.y + v2.y + v3.y;
            a0.z += v0.z + v1.z + v2.z + v3.z;
            a0.w += v0.w + v1.w + v2.w + v3.w;
            if (hi) {
                a1.x += u0.x + u1.x + u2.x + u3.x;
                a1.y += u0.y + u1.y + u2.y + u3.y;
                a1.z += u0.z + u1.z + u2.z + u3.z;
                a1.w += u0.w + u1.w + u2.w + u3.w;
            }
        }
        for (; i < len; i++) {                   // tail members
            const float4* b = xq + (size_t)lst[i] * SAMPLE_F4;
            float4 v = __ldg(b + tid);
            a0.x += v.x; a0.y += v.y; a0.z += v.z; a0.w += v.w;
            if (hi) {
                float4 u = __ldg(b + THREADS + tid);
                a1.x += u.x; a1.y += u.y; a1.z += u.z; a1.w += u.w;
            }
        }

        red4[tid] = a0;
        if (hi) red4[THREADS + tid] = a1;
        __syncthreads();

        // 1568 floats -> 32 channel sums (stride 49: odd => conflict-free)
        if (tid < CHB) {
            const float* __restrict__ r = (const float*)red4 + tid * HW;
            float s = 0.f;
            #pragma unroll
            for (int k = 0; k < HW; k++) s += r[k];
            atomicAdd(&out[g * N_CHAN + q * CHB + tid], s * g_recip[g]);
        }
    }

    // ---------------- arrive; last arrival resets flag ----------------
    if (tid == 0) {
        int n = atomicAdd(&g_arr[g], 1);
        if (n == CTAS_PER_GROUP - 1) {
            atomicExch(&g_arr[g], 0);
            atomicExch(&g_flag[g], 0);           // ready for next replay
        }
    }
}

extern "C" void kernel_launch(void* const* d_in, const int* in_sizes, int n_in,
                              void* d_out, int out_size)
{
    const float* x   = (const float*)d_in[0];
    const int*   idx = (const int*)d_in[1];
    float*       out = (float*)d_out;

    (void)in_sizes; (void)n_in; (void)out_size;

    fused_kernel<<<GRID, THREADS>>>(x, idx, out);
}

// round 14
// speedup vs baseline: 1.0063x; 1.0063x over previous
#include <cuda_runtime.h>
#include <cstdint>

#define N_SAMPLES 2048
#define N_CHAN    512
#define HW        49
#define N_GROUPS  64
#define CHB       32                        // channels per chunk: 6272B strip, 128B-aligned
#define QCH       (N_CHAN / CHB)            // 16
#define NB        16                        // samples per CTA block
#define GRID1     ((N_SAMPLES / NB) * QCH)  // 2048
#define T1        256
#define STRIP_F4  392                       // CHB*HW/4
#define SAMPLE_F4 (N_CHAN * HW / 4)         // 6272
#define NBUF      4

#define T2        128
#define GRID2     (N_GROUPS * (N_CHAN / T2))  // 256

// Per-sample channel sums. Every element rewritten each replay -> no init.
__device__ float g_xs[N_SAMPLES][N_CHAN];   // 4 MB

__device__ __forceinline__ uint32_t smem_u32(const void* p) {
    return (uint32_t)__cvta_generic_to_shared(p);
}
__device__ __forceinline__ void cp_async16(uint32_t s, const void* g) {
    asm volatile("cp.async.cg.shared.global [%0], [%1], 16;\n"
                 :: "r"(s), "l"(g) : "memory");
}
__device__ __forceinline__ void cp_commit() {
    asm volatile("cp.async.commit_group;\n" ::: "memory");
}
__device__ __forceinline__ void cp_wait3() {
    asm volatile("cp.async.wait_group 3;\n" ::: "memory");
}

// ---------------------------------------------------------------------------
// Kernel 1 (idx-independent, perfectly uniform): CTA = (sample block, chunk).
// Streams 16 consecutive samples' 6272-byte strips through a 4-slot cp.async
// ring; per member reduce 32 channels with 8 lanes each; STG per-sample sums.
// ---------------------------------------------------------------------------
__global__ __launch_bounds__(T1) void sample_sum_kernel(
    const float* __restrict__ x)
{
    __shared__ float4 buf[NBUF][STRIP_F4];      // 25088 B

    const int q   = blockIdx.x & (QCH - 1);
    const int nb  = blockIdx.x >> 4;            // 0..127
    const int n0  = nb * NB;
    const int tid = threadIdx.x;
    const bool hi = (tid < STRIP_F4 - T1);      // tid < 136: second float4
    const int cc  = tid >> 3;                   // channel 0..31
    const int r   = tid & 7;                    // lane-in-octet

    const float4* __restrict__ xq = (const float4*)x + (size_t)q * STRIP_F4;

    // prologue: stage members 0..NBUF-2
    #pragma unroll
    for (int p = 0; p < NBUF - 1; p++) {
        const float4* src = xq + (size_t)(n0 + p) * SAMPLE_F4;
        cp_async16(smem_u32(&buf[p][tid]), src + tid);
        if (hi) cp_async16(smem_u32(&buf[p][T1 + tid]), src + T1 + tid);
        cp_commit();
    }

    for (int j = 0; j < NB; j++) {
        const int jj = j + NBUF - 1;
        if (jj < NB) {
            const float4* src = xq + (size_t)(n0 + jj) * SAMPLE_F4;
            const int slot = jj & (NBUF - 1);
            cp_async16(smem_u32(&buf[slot][tid]), src + tid);
            if (hi) cp_async16(smem_u32(&buf[slot][T1 + tid]), src + T1 + tid);
        }
        cp_commit();                            // empty group when jj>=NB
        cp_wait3();                             // member j's group complete
        __syncthreads();                        // cross-thread visibility

        // reduce member j: 32 channels x 8 lanes, stride-8 over 49 floats
        const float* base = (const float*)&buf[j & (NBUF - 1)][0] + cc * HW;
        float s = 0.0f;
        #pragma unroll
        for (int k = 0; k < 7; k++) {
            int e = r + 8 * k;
            if (e < HW) s += base[e];
        }
        s += __shfl_down_sync(0xFFFFFFFFu, s, 4, 8);
        s += __shfl_down_sync(0xFFFFFFFFu, s, 2, 8);
        s += __shfl_down_sync(0xFFFFFFFFu, s, 1, 8);
        if (r == 0) g_xs[n0 + j][q * CHB + cc] = s;

        __syncthreads();                        // slot reused next iteration
    }
}

// ---------------------------------------------------------------------------
// Kernel 2: CTA = (group g, 128-channel chunk). Scan idx (L2), compact
// members, sum their xs rows (L2-resident), write mean exactly once.
// ---------------------------------------------------------------------------
__global__ __launch_bounds__(T2) void segment_kernel(
    const int* __restrict__ idx, float* __restrict__ out)
{
    __shared__ unsigned short list[N_SAMPLES];
    __shared__ int s_cnt;

    const int g     = blockIdx.x >> 2;
    const int chunk = blockIdx.x & 3;
    const int tid   = threadIdx.x;

    if (tid == 0) s_cnt = 0;
    __syncthreads();

    const int4* __restrict__ idx4 = (const int4*)idx;
    for (int i = tid; i < N_SAMPLES / 4; i += T2) {
        int4 v = idx4[i];
        int  b = 4 * i;
        if (v.x == g) list[atomicAdd(&s_cnt, 1)] = (unsigned short)(b + 0);
        if (v.y == g) list[atomicAdd(&s_cnt, 1)] = (unsigned short)(b + 1);
        if (v.z == g) list[atomicAdd(&s_cnt, 1)] = (unsigned short)(b + 2);
        if (v.w == g) list[atomicAdd(&s_cnt, 1)] = (unsigned short)(b + 3);
    }
    __syncthreads();
    const int cnt = s_cnt;

    const int c = chunk * T2 + tid;             // this thread's channel

    float a0 = 0.f, a1 = 0.f, a2 = 0.f, a3 = 0.f;
    int i = 0;
    for (; i + 4 <= cnt; i += 4) {              // 4 members front-batched
        a0 += g_xs[list[i + 0]][c];
        a1 += g_xs[list[i + 1]][c];
        a2 += g_xs[list[i + 2]][c];
        a3 += g_xs[list[i + 3]][c];
    }
    for (; i < cnt; i++) a0 += g_xs[list[i]][c];

    float total = (a0 + a1) + (a2 + a3);
    out[g * N_CHAN + c] = total / ((float)cnt * (float)HW);
}

extern "C" void kernel_launch(void* const* d_in, const int* in_sizes, int n_in,
                              void* d_out, int out_size)
{
    const float* x   = (const float*)d_in[0];
    const int*   idx = (const int*)d_in[1];
    float*       out = (float*)d_out;

    (void)in_sizes; (void)n_in; (void)out_size;

    sample_sum_kernel<<<GRID1, T1>>>(x);
    segment_kernel<<<GRID2, T2>>>(idx, out);
}

// round 15
// speedup vs baseline: 1.1633x; 1.1560x over previous
#include <cuda_runtime.h>
#include <cstdint>

#define N_SAMPLES 2048
#define N_CHAN    512
#define HW        49
#define N_GROUPS  64
#define CHB       32                        // channels per chunk: 6272B strip, 128B-aligned
#define QCH       (N_CHAN / CHB)            // 16
#define NB        16                        // samples per CTA block
#define GRID1     ((N_SAMPLES / NB) * QCH)  // 2048
#define T1        256
#define STRIP_F4  392                       // CHB*HW/4
#define SAMPLE_F4 (N_CHAN * HW / 4)         // 6272
#define NBUF      4

// Per-group 1/(count*49), rebuilt by prep every replay.
__device__ float g_recip[N_GROUPS];

__device__ __forceinline__ uint32_t smem_u32(const void* p) {
    return (uint32_t)__cvta_generic_to_shared(p);
}
__device__ __forceinline__ void cp_async16(uint32_t s, const void* g) {
    asm volatile("cp.async.cg.shared.global [%0], [%1], 16;\n"
                 :: "r"(s), "l"(g) : "memory");
}
__device__ __forceinline__ void cp_commit() {
    asm volatile("cp.async.commit_group;\n" ::: "memory");
}
__device__ __forceinline__ void cp_wait3() {
    asm volatile("cp.async.wait_group 3;\n" ::: "memory");
}

// ---------------------------------------------------------------------------
// Prep: one CTA per group. Zero out row g, count group members, publish recip.
// ---------------------------------------------------------------------------
__global__ __launch_bounds__(T1) void prep_kernel(
    const int* __restrict__ idx, float* __restrict__ out)
{
    __shared__ int s_total;
    const int g   = blockIdx.x;
    const int tid = threadIdx.x;

    if (tid == 0) s_total = 0;
    __syncthreads();

    float4* o4 = (float4*)(out + g * N_CHAN);
    if (tid < N_CHAN / 4) o4[tid] = make_float4(0.f, 0.f, 0.f, 0.f);

    int cnt = 0;
    const int4* __restrict__ idx4 = (const int4*)idx;
    for (int i = tid; i < N_SAMPLES / 4; i += T1) {
        int4 v = idx4[i];
        cnt += (v.x == g) + (v.y == g) + (v.z == g) + (v.w == g);
    }
    cnt += __shfl_down_sync(0xFFFFFFFFu, cnt, 16);
    cnt += __shfl_down_sync(0xFFFFFFFFu, cnt, 8);
    cnt += __shfl_down_sync(0xFFFFFFFFu, cnt, 4);
    cnt += __shfl_down_sync(0xFFFFFFFFu, cnt, 2);
    cnt += __shfl_down_sync(0xFFFFFFFFu, cnt, 1);
    if ((tid & 31) == 0) atomicAdd(&s_total, cnt);
    __syncthreads();

    if (tid == 0) g_recip[g] = 1.0f / ((float)s_total * (float)HW);
}

// ---------------------------------------------------------------------------
// Main (idx-independent streaming, measured ~76% DRAM): CTA = (sample block,
// 32-channel chunk). Streams 16 consecutive samples' 6272-byte strips through
// a 4-slot cp.async ring; per member reduce 32 channels with 8 lanes each;
// epilogue: prescaled atomicAdd straight into out[idx[n]] (1M spread REDG).
// ---------------------------------------------------------------------------
__global__ __launch_bounds__(T1) void sample_sum_kernel(
    const float* __restrict__ x,
    const int*   __restrict__ idx,
    float*       __restrict__ out)
{
    __shared__ float4 buf[NBUF][STRIP_F4];      // 25088 B

    const int q   = blockIdx.x & (QCH - 1);
    const int nb  = blockIdx.x >> 4;            // 0..127
    const int n0  = nb * NB;
    const int tid = threadIdx.x;
    const bool hi = (tid < STRIP_F4 - T1);      // tid < 136: second float4
    const int cc  = tid >> 3;                   // channel 0..31
    const int r   = tid & 7;                    // lane-in-octet

    const float4* __restrict__ xq = (const float4*)x + (size_t)q * STRIP_F4;

    // prologue: stage members 0..NBUF-2
    #pragma unroll
    for (int p = 0; p < NBUF - 1; p++) {
        const float4* src = xq + (size_t)(n0 + p) * SAMPLE_F4;
        cp_async16(smem_u32(&buf[p][tid]), src + tid);
        if (hi) cp_async16(smem_u32(&buf[p][T1 + tid]), src + T1 + tid);
        cp_commit();
    }

    for (int j = 0; j < NB; j++) {
        const int jj = j + NBUF - 1;
        if (jj < NB) {
            const float4* src = xq + (size_t)(n0 + jj) * SAMPLE_F4;
            const int slot = jj & (NBUF - 1);
            cp_async16(smem_u32(&buf[slot][tid]), src + tid);
            if (hi) cp_async16(smem_u32(&buf[slot][T1 + tid]), src + T1 + tid);
        }
        cp_commit();                            // empty group when jj>=NB
        cp_wait3();                             // member j's group complete
        __syncthreads();                        // cross-thread visibility

        // reduce member j: 32 channels x 8 lanes, stride-8 over 49 floats
        const float* base = (const float*)&buf[j & (NBUF - 1)][0] + cc * HW;
        float s = 0.0f;
        #pragma unroll
        for (int k = 0; k < 7; k++) {
            int e = r + 8 * k;
            if (e < HW) s += base[e];
        }
        s += __shfl_down_sync(0xFFFFFFFFu, s, 4, 8);
        s += __shfl_down_sync(0xFFFFFFFFu, s, 2, 8);
        s += __shfl_down_sync(0xFFFFFFFFu, s, 1, 8);

        if (r == 0) {
            const int g = __ldg(&idx[n0 + j]);
            atomicAdd(&out[g * N_CHAN + q * CHB + cc],
                      s * __ldg(&g_recip[g]));
        }
        __syncthreads();                        // slot reused next iteration
    }
}

extern "C" void kernel_launch(void* const* d_in, const int* in_sizes, int n_in,
                              void* d_out, int out_size)
{
    const float* x   = (const float*)d_in[0];
    const int*   idx = (const int*)d_in[1];
    float*       out = (float*)d_out;

    (void)in_sizes; (void)n_in; (void)out_size;

    prep_kernel<<<N_GROUPS, T1>>>(idx, out);
    sample_sum_kernel<<<GRID1, T1>>>(x, idx, out);
}

// round 16
// speedup vs baseline: 1.1757x; 1.0107x over previous
#include <cuda_runtime.h>
#include <cstdint>

#define N_SAMPLES 2048
#define N_CHAN    512
#define HW        49
#define N_GROUPS  64
#define CHB       32                        // channels per chunk: 6272B strip, 128B-aligned
#define QCH       (N_CHAN / CHB)            // 16
#define NB        16                        // samples per CTA block
#define GRID1     ((N_SAMPLES / NB) * QCH)  // 2048
#define T1        256
#define STRIP_F4  392                       // CHB*HW/4
#define SAMPLE_F4 (N_CHAN * HW / 4)         // 6272 float4 per sample
#define STRIP_B   (STRIP_F4 * 16)           // 6272 bytes per strip
#define NBUF      4

// Per-group 1/(count*49), rebuilt by prep every replay.
__device__ float g_recip[N_GROUPS];

__device__ __forceinline__ uint32_t smem_u32(const void* p) {
    return (uint32_t)__cvta_generic_to_shared(p);
}
__device__ __forceinline__ void mbar_init(uint32_t a, uint32_t cnt) {
    asm volatile("mbarrier.init.shared.b64 [%0], %1;" :: "r"(a), "r"(cnt) : "memory");
}
__device__ __forceinline__ void mbar_expect_tx(uint32_t a, uint32_t bytes) {
    asm volatile("mbarrier.arrive.expect_tx.shared.b64 _, [%0], %1;"
                 :: "r"(a), "r"(bytes) : "memory");
}
__device__ __forceinline__ void bulk_g2s(uint32_t dst, const void* src,
                                         uint32_t bytes, uint32_t mbar) {
    asm volatile(
        "cp.async.bulk.shared::cta.global.mbarrier::complete_tx::bytes "
        "[%0], [%1], %2, [%3];"
        :: "r"(dst), "l"(src), "r"(bytes), "r"(mbar) : "memory");
}
__device__ __forceinline__ void mbar_wait(uint32_t a, uint32_t parity) {
    asm volatile(
        "{\n\t"
        ".reg .pred P;\n\t"
        "WL_%=:\n\t"
        "mbarrier.try_wait.parity.acquire.cta.shared::cta.b64 P, [%0], %1, 0x989680;\n\t"
        "@P bra WD_%=;\n\t"
        "bra WL_%=;\n\t"
        "WD_%=:\n\t"
        "}"
        :: "r"(a), "r"(parity) : "memory");
}

// ---------------------------------------------------------------------------
// Prep: one CTA per group. Zero out row g, count group members, publish recip.
// ---------------------------------------------------------------------------
__global__ __launch_bounds__(T1) void prep_kernel(
    const int* __restrict__ idx, float* __restrict__ out)
{
    __shared__ int s_total;
    const int g   = blockIdx.x;
    const int tid = threadIdx.x;

    if (tid == 0) s_total = 0;
    __syncthreads();

    float4* o4 = (float4*)(out + g * N_CHAN);
    if (tid < N_CHAN / 4) o4[tid] = make_float4(0.f, 0.f, 0.f, 0.f);

    int cnt = 0;
    const int4* __restrict__ idx4 = (const int4*)idx;
    for (int i = tid; i < N_SAMPLES / 4; i += T1) {
        int4 v = idx4[i];
        cnt += (v.x == g) + (v.y == g) + (v.z == g) + (v.w == g);
    }
    cnt += __shfl_down_sync(0xFFFFFFFFu, cnt, 16);
    cnt += __shfl_down_sync(0xFFFFFFFFu, cnt, 8);
    cnt += __shfl_down_sync(0xFFFFFFFFu, cnt, 4);
    cnt += __shfl_down_sync(0xFFFFFFFFu, cnt, 2);
    cnt += __shfl_down_sync(0xFFFFFFFFu, cnt, 1);
    if ((tid & 31) == 0) atomicAdd(&s_total, cnt);
    __syncthreads();

    if (tid == 0) g_recip[g] = 1.0f / ((float)s_total * (float)HW);
}

// ---------------------------------------------------------------------------
// Main: CTA = (16-sample block, 32-channel chunk). tid 0 streams each
// member's 6272-byte strip with ONE cp.async.bulk into a 4-slot ring;
// completion via mbarrier expect_tx; consumers acquire-wait, reduce 32
// channels with 8 lanes each, prescaled atomicAdd into out[idx[n]].
// Slot-reuse safety: the single per-member __syncthreads orders all reads of
// slot s before the (later-issued) bulk that overwrites s; the same barrier
// guarantees no mbarrier parity aliasing.
// ---------------------------------------------------------------------------
__global__ __launch_bounds__(T1) void sample_sum_kernel(
    const float* __restrict__ x,
    const int*   __restrict__ idx,
    float*       __restrict__ out)
{
    __shared__ float4   buf[NBUF][STRIP_F4];      // 25088 B, 16B-aligned slots
    __shared__ uint64_t mbar[NBUF];

    const int q   = blockIdx.x & (QCH - 1);
    const int nb  = blockIdx.x >> 4;
    const int n0  = nb * NB;
    const int tid = threadIdx.x;
    const int cc  = tid >> 3;                     // channel 0..31
    const int r   = tid & 7;                      // lane-in-octet

    const char* __restrict__ xb =
        (const char*)x + ((size_t)n0 * SAMPLE_F4 + (size_t)q * STRIP_F4) * 16;

    if (tid == 0) {
        #pragma unroll
        for (int s = 0; s < NBUF; s++)
            mbar_init(smem_u32(&mbar[s]), 1);
    }
    __syncthreads();                              // init visible to all

    // prologue: stage members 0..NBUF-2
    if (tid == 0) {
        #pragma unroll
        for (int p = 0; p < NBUF - 1; p++) {
            mbar_expect_tx(smem_u32(&mbar[p]), STRIP_B);
            bulk_g2s(smem_u32(&buf[p][0]), xb + (size_t)p * (SAMPLE_F4 * 16),
                     STRIP_B, smem_u32(&mbar[p]));
        }
    }

    for (int j = 0; j < NB; j++) {
        const int s = j & (NBUF - 1);
        mbar_wait(smem_u32(&mbar[s]), (j >> 2) & 1);   // member j landed

        // reduce member j: 32 channels x 8 lanes, stride-8 over 49 floats
        const float* base = (const float*)&buf[s][0] + cc * HW;
        float sum = 0.0f;
        #pragma unroll
        for (int k = 0; k < 7; k++) {
            int e = r + 8 * k;
            if (e < HW) sum += base[e];
        }
        sum += __shfl_down_sync(0xFFFFFFFFu, sum, 4, 8);
        sum += __shfl_down_sync(0xFFFFFFFFu, sum, 2, 8);
        sum += __shfl_down_sync(0xFFFFFFFFu, sum, 1, 8);

        if (r == 0) {
            const int g = __ldg(&idx[n0 + j]);
            atomicAdd(&out[g * N_CHAN + q * CHB + cc],
                      sum * __ldg(&g_recip[g]));
        }

        __syncthreads();                          // all reads of ring done

        const int jj = j + NBUF - 1;              // refill slot (j+3)&3
        if (tid == 0 && jj < NB) {
            const int ss = jj & (NBUF - 1);
            mbar_expect_tx(smem_u32(&mbar[ss]), STRIP_B);
            bulk_g2s(smem_u32(&buf[ss][0]),
                     xb + (size_t)jj * (SAMPLE_F4 * 16),
                     STRIP_B, smem_u32(&mbar[ss]));
        }
    }
}

extern "C" void kernel_launch(void* const* d_in, const int* in_sizes, int n_in,
                              void* d_out, int out_size)
{
    const float* x   = (const float*)d_in[0];
    const int*   idx = (const int*)d_in[1];
    float*       out = (float*)d_out;

    (void)in_sizes; (void)n_in; (void)out_size;

    prep_kernel<<<N_GROUPS, T1>>>(idx, out);
    sample_sum_kernel<<<GRID1, T1>>>(x, idx, out);
}

// round 17
// speedup vs baseline: 1.1923x; 1.0142x over previous
#include <cuda_runtime.h>
#include <cstdint>

#define N_SAMPLES 2048
#define N_CHAN    512
#define HW        49
#define N_GROUPS  64
#define CHB       32                        // channels per chunk: 6272B strip, 128B-aligned
#define QCH       (N_CHAN / CHB)            // 16
#define NB        16                        // samples per CTA block
#define GRID1     ((N_SAMPLES / NB) * QCH)  // 2048
#define T1        256
#define STRIP_F4  392                       // CHB*HW/4
#define SAMPLE_F4 (N_CHAN * HW / 4)         // 6272 float4 per sample
#define STRIP_B   (STRIP_F4 * 16)           // 6272 bytes per strip
#define NBUF      4

// Per-group 1/(count*49), rebuilt by prep every replay.
__device__ float g_recip[N_GROUPS];

__device__ __forceinline__ uint32_t smem_u32(const void* p) {
    return (uint32_t)__cvta_generic_to_shared(p);
}
__device__ __forceinline__ void mbar_init(uint32_t a, uint32_t cnt) {
    asm volatile("mbarrier.init.shared.b64 [%0], %1;" :: "r"(a), "r"(cnt) : "memory");
}
__device__ __forceinline__ void mbar_expect_tx(uint32_t a, uint32_t bytes) {
    asm volatile("mbarrier.arrive.expect_tx.shared.b64 _, [%0], %1;"
                 :: "r"(a), "r"(bytes) : "memory");
}
__device__ __forceinline__ void bulk_g2s(uint32_t dst, const void* src,
                                         uint32_t bytes, uint32_t mbar) {
    asm volatile(
        "cp.async.bulk.shared::cta.global.mbarrier::complete_tx::bytes "
        "[%0], [%1], %2, [%3];"
        :: "r"(dst), "l"(src), "r"(bytes), "r"(mbar) : "memory");
}
__device__ __forceinline__ void mbar_wait(uint32_t a, uint32_t parity) {
    asm volatile(
        "{\n\t"
        ".reg .pred P;\n\t"
        "WL_%=:\n\t"
        "mbarrier.try_wait.parity.acquire.cta.shared::cta.b64 P, [%0], %1, 0x989680;\n\t"
        "@P bra WD_%=;\n\t"
        "bra WL_%=;\n\t"
        "WD_%=:\n\t"
        "}"
        :: "r"(a), "r"(parity) : "memory");
}

// ---------------------------------------------------------------------------
// Prep (lean): CTA 0 histograms idx ONCE and writes all recips;
// CTAs 1..64 zero their group's out row. No redundant scans.
// ---------------------------------------------------------------------------
__global__ __launch_bounds__(T1) void prep_kernel(
    const int* __restrict__ idx, float* __restrict__ out)
{
    const int tid = threadIdx.x;

    if (blockIdx.x > 0) {                   // zero out row (g = bid-1)
        float4* o4 = (float4*)(out + (blockIdx.x - 1) * N_CHAN);
        if (tid < N_CHAN / 4) o4[tid] = make_float4(0.f, 0.f, 0.f, 0.f);
        return;
    }

    __shared__ int h[N_GROUPS];
    if (tid < N_GROUPS) h[tid] = 0;
    __syncthreads();

    const int4* __restrict__ idx4 = (const int4*)idx;
    for (int i = tid; i < N_SAMPLES / 4; i += T1) {
        int4 v = idx4[i];
        atomicAdd(&h[v.x], 1);
        atomicAdd(&h[v.y], 1);
        atomicAdd(&h[v.z], 1);
        atomicAdd(&h[v.w], 1);
    }
    __syncthreads();

    if (tid < N_GROUPS)
        g_recip[tid] = 1.0f / ((float)h[tid] * (float)HW);
}

// ---------------------------------------------------------------------------
// Main (at the measured memory plateau — unchanged from R16): CTA =
// (16-sample block, 32-channel chunk). tid 0 streams each member's 6272-byte
// strip with ONE cp.async.bulk into a 4-slot ring; mbarrier expect_tx
// completion; consumers acquire-wait, reduce 32 channels with 8 lanes each,
// prescaled atomicAdd into out[idx[n]].
// ---------------------------------------------------------------------------
__global__ __launch_bounds__(T1) void sample_sum_kernel(
    const float* __restrict__ x,
    const int*   __restrict__ idx,
    float*       __restrict__ out)
{
    __shared__ float4   buf[NBUF][STRIP_F4];      // 25088 B, 16B-aligned slots
    __shared__ uint64_t mbar[NBUF];

    const int q   = blockIdx.x & (QCH - 1);
    const int nb  = blockIdx.x >> 4;
    const int n0  = nb * NB;
    const int tid = threadIdx.x;
    const int cc  = tid >> 3;                     // channel 0..31
    const int r   = tid & 7;                      // lane-in-octet

    const char* __restrict__ xb =
        (const char*)x + ((size_t)n0 * SAMPLE_F4 + (size_t)q * STRIP_F4) * 16;

    if (tid == 0) {
        #pragma unroll
        for (int s = 0; s < NBUF; s++)
            mbar_init(smem_u32(&mbar[s]), 1);
    }
    __syncthreads();                              // init visible to all

    // prologue: stage members 0..NBUF-2
    if (tid == 0) {
        #pragma unroll
        for (int p = 0; p < NBUF - 1; p++) {
            mbar_expect_tx(smem_u32(&mbar[p]), STRIP_B);
            bulk_g2s(smem_u32(&buf[p][0]), xb + (size_t)p * (SAMPLE_F4 * 16),
                     STRIP_B, smem_u32(&mbar[p]));
        }
    }

    for (int j = 0; j < NB; j++) {
        const int s = j & (NBUF - 1);
        mbar_wait(smem_u32(&mbar[s]), (j >> 2) & 1);   // member j landed

        // reduce member j: 32 channels x 8 lanes, stride-8 over 49 floats
        const float* base = (const float*)&buf[s][0] + cc * HW;
        float sum = 0.0f;
        #pragma unroll
        for (int k = 0; k < 7; k++) {
            int e = r + 8 * k;
            if (e < HW) sum += base[e];
        }
        sum += __shfl_down_sync(0xFFFFFFFFu, sum, 4, 8);
        sum += __shfl_down_sync(0xFFFFFFFFu, sum, 2, 8);
        sum += __shfl_down_sync(0xFFFFFFFFu, sum, 1, 8);

        if (r == 0) {
            const int g = __ldg(&idx[n0 + j]);
            atomicAdd(&out[g * N_CHAN + q * CHB + cc],
                      sum * __ldg(&g_recip[g]));
        }

        __syncthreads();                          // all reads of ring done

        const int jj = j + NBUF - 1;              // refill slot (j+3)&3
        if (tid == 0 && jj < NB) {
            const int ss = jj & (NBUF - 1);
            mbar_expect_tx(smem_u32(&mbar[ss]), STRIP_B);
            bulk_g2s(smem_u32(&buf[ss][0]),
                     xb + (size_t)jj * (SAMPLE_F4 * 16),
                     STRIP_B, smem_u32(&mbar[ss]));
        }
    }
}

extern "C" void kernel_launch(void* const* d_in, const int* in_sizes, int n_in,
                              void* d_out, int out_size)
{
    const float* x   = (const float*)d_in[0];
    const int*   idx = (const int*)d_in[1];
    float*       out = (float*)d_out;

    (void)in_sizes; (void)n_in; (void)out_size;

    prep_kernel<<<N_GROUPS + 1, T1>>>(idx, out);
    sample_sum_kernel<<<GRID1, T1>>>(x, idx, out);
}